// round 14
// baseline (speedup 1.0000x reference)
#include <cuda_runtime.h>
#include <cuda_fp16.h>
#include <cstdint>

#define NNODES 50000
#define EDGES  800000
#define HDIM   256

// ---------------- scratch (no allocations allowed) ----------------
__device__ __half g_actA[NNODES * HDIM];
__device__ __half g_actB[NNODES * HDIM];
__device__ __half g_hwh[NNODES * HDIM];    // GEMM out for convs; also holds x16 for encoder
__device__ __half g_Wh[4][65536];
__device__ int    g_deg[NNODES];
__device__ float  g_dinv[NNODES];
__device__ int    g_offs[NNODES + 1];
__device__ int    g_cur[NNODES];
__device__ int    g_bsum[256];
__device__ int2   g_csr[EDGES];            // .x = src node, .y = dinv[src] bits

// ---------------- fused prep: deg_zero + 4x weight transpose + x->fp16 ----------------
__global__ void prep_kernel(const float* __restrict__ enc_W, const float* __restrict__ W1,
                            const float* __restrict__ W2, const float* __restrict__ W3,
                            __half* __restrict__ WhBase,
                            int* __restrict__ deg,
                            const float* __restrict__ x, __half* __restrict__ xh,
                            int M)
{
    int i = blockIdx.x * 256 + threadIdx.x;
    if (i < 229376) {
        const float* W; __half* Wh; int K; int idx;
        if (i < 32768)       { W = enc_W; Wh = WhBase;              K = 128; idx = i; }
        else if (i < 98304)  { W = W1;    Wh = WhBase + 65536;      K = 256; idx = i - 32768; }
        else if (i < 163840) { W = W2;    Wh = WhBase + 2 * 65536;  K = 256; idx = i - 98304; }
        else                 { W = W3;    Wh = WhBase + 3 * 65536;  K = 256; idx = i - 163840; }
        int n = idx / K, k = idx - n * K;
        Wh[idx] = __float2half_rn(W[k * 256 + n]);
    } else if (i < 279376) {
        int node = i - 229376;
        if (node < M) deg[node] = 0;
    } else {
        int f4 = i - 279376;
        if (f4 < M * 32) {
            float4 v = *(const float4*)(x + 4 * (size_t)f4);
            __half2 a = __floats2half2_rn(v.x, v.y);
            __half2 b = __floats2half2_rn(v.z, v.w);
            *(uint2*)(xh + 4 * (size_t)f4) = make_uint2(*(uint32_t*)&a, *(uint32_t*)&b);
        }
    }
}

__global__ void deg_count_kernel(int* __restrict__ deg, const int* __restrict__ dst, int E) {
    int e = blockIdx.x * blockDim.x + threadIdx.x;
    if (e < E) atomicAdd(&deg[dst[e]], 1);
}

// ---------------- 3-pass scan (multi-block); dinv fused into pass 3 ----------------
__global__ void scan1_kernel(const int* __restrict__ deg, int* __restrict__ offs,
                             int* __restrict__ bsum, int n)
{
    __shared__ int sh[256];
    const int t = threadIdx.x;
    const int i = blockIdx.x * 256 + t;
    int v = (i < n) ? deg[i] : 0;
    sh[t] = v;
    __syncthreads();
#pragma unroll
    for (int off = 1; off < 256; off <<= 1) {
        int x = (t >= off) ? sh[t - off] : 0;
        __syncthreads();
        sh[t] += x;
        __syncthreads();
    }
    if (i < n) offs[i] = sh[t] - v;
    if (t == 255) bsum[blockIdx.x] = sh[255];
}

__global__ void scan2_kernel(int* __restrict__ bsum, int* __restrict__ offs, int nb, int n)
{
    __shared__ int sh[256];
    const int t = threadIdx.x;
    int v = (t < nb) ? bsum[t] : 0;
    sh[t] = v;
    __syncthreads();
#pragma unroll
    for (int off = 1; off < 256; off <<= 1) {
        int x = (t >= off) ? sh[t - off] : 0;
        __syncthreads();
        sh[t] += x;
        __syncthreads();
    }
    if (t < nb) bsum[t] = sh[t] - v;
    if (t == 255) offs[n] = sh[255];
}

__global__ void scan3_kernel(int* __restrict__ offs, int* __restrict__ cur,
                             float* __restrict__ dinv, const int* __restrict__ deg,
                             const int* __restrict__ bsum, int n)
{
    int i = blockIdx.x * blockDim.x + threadIdx.x;
    if (i < n) {
        int o = offs[i] + bsum[i >> 8];
        offs[i] = o;
        cur[i]  = o;
        dinv[i] = rsqrtf((float)(deg[i] + 1));   // +1 self-loop
    }
}

// ---------------- CSR fill (packed src+weight) ----------------
__global__ void csr_fill_kernel(int* __restrict__ cur, int2* __restrict__ csr,
                                const int* __restrict__ src, const int* __restrict__ dst,
                                const float* __restrict__ dinv, int E)
{
    int e = blockIdx.x * blockDim.x + threadIdx.x;
    if (e >= E) return;
    int s = src[e];
    int p = atomicAdd(&cur[dst[e]], 1);
    csr[p] = make_int2(s, __float_as_int(dinv[s]));
}

// ---------------- fp16 tensor-core GEMM: wide-N 128x256 tile, 3-stage cp.async ----------------
// C[M,256] = A[M,K] @ W[K,256] (+bias). 256 threads = 8 warps (4m x 2n), warp tile 32x128.
__device__ __forceinline__ void mma_f16(float* c, const uint32_t* a, uint32_t b0, uint32_t b1) {
    asm volatile("mma.sync.aligned.m16n8k16.row.col.f32.f16.f16.f32 "
        "{%0,%1,%2,%3}, {%4,%5,%6,%7}, {%8,%9}, {%0,%1,%2,%3};"
        : "+f"(c[0]), "+f"(c[1]), "+f"(c[2]), "+f"(c[3])
        : "r"(a[0]), "r"(a[1]), "r"(a[2]), "r"(a[3]), "r"(b0), "r"(b1));
}

__device__ __forceinline__ void ldm_x4(uint32_t* r, uint32_t saddr) {
    asm volatile("ldmatrix.sync.aligned.m8n8.x4.shared.b16 {%0,%1,%2,%3}, [%4];"
        : "=r"(r[0]), "=r"(r[1]), "=r"(r[2]), "=r"(r[3]) : "r"(saddr));
}

__device__ __forceinline__ void cpa16(uint32_t saddr, const void* gaddr, int szr) {
    asm volatile("cp.async.cg.shared.global [%0], [%1], 16, %2;"
        :: "r"(saddr), "l"(gaddr), "r"(szr));
}

#define GEMM_SMEM (3 * 128 * 48 + 3 * 256 * 48)   // sA 18KB + sB 36KB = 54KB

template <int K, bool BIAS>
__global__ void __launch_bounds__(256) gemm_f16_kernel(
    const __half* __restrict__ A, const __half* __restrict__ Wh,
    const float* __restrict__ bias, __half* __restrict__ Cout, int M)
{
    extern __shared__ __half smem[];
    const uint32_t sA_base = (uint32_t)__cvta_generic_to_shared(smem);
    const uint32_t sB_base = sA_base + 3 * 128 * 48;
    const uint32_t bufA = 128 * 48, bufB = 256 * 48;

    const int tid  = threadIdx.x;
    const int lane = tid & 31;
    const int wid  = tid >> 5;
    const int wm   = wid >> 1;            // 0..3 (m 32-group)
    const int wn   = wid & 1;             // 0..1 (n 128-group)
    const int g    = lane >> 2;
    const int tg   = lane & 3;
    const int row0 = blockIdx.x * 128;

    // A loader: 128 rows x 32B per stage = 256 chunks -> 1/thread
    const int ar  = tid >> 1;
    const int ak8 = (tid & 1) * 8;
    // B loader: 256 rows x 32B per stage = 512 chunks -> 2/thread
    const int br  = tid >> 1;             // rows 0..127 (+128 on second chunk)
    const int bk8 = (tid & 1) * 8;

    const int arow = row0 + ar;
    const int asz  = (arow < M) ? 16 : 0;
    const __half* Aptr  = A + (size_t)arow * K + ak8;
    const __half* Bptr0 = Wh + (size_t)br * K + bk8;
    const __half* Bptr1 = Wh + (size_t)(br + 128) * K + bk8;

    const uint32_t ast  = sA_base + ar * 48 + ak8 * 2;
    const uint32_t bst0 = sB_base + br * 48 + bk8 * 2;
    const uint32_t bst1 = sB_base + (br + 128) * 48 + bk8 * 2;

    const int l8 = lane & 7;
    const int a_r = ((lane >> 3) & 1) * 8 + l8;
    const int a_k = (lane >> 4) * 8;
    const int b_n = ((lane >> 4) & 1) * 8 + l8;
    const int b_k = ((lane >> 3) & 1) * 8;
    const uint32_t aoff0 = (uint32_t)((wm * 32 + a_r) * 48 + a_k * 2);
    const uint32_t boff0 = (uint32_t)((wn * 128 + b_n) * 48 + b_k * 2);

    float acc[2][16][4];
#pragma unroll
    for (int mt = 0; mt < 2; mt++)
#pragma unroll
        for (int nt = 0; nt < 16; nt++)
#pragma unroll
            for (int r = 0; r < 4; r++) acc[mt][nt][r] = 0.f;

    const int NT = K / 16;

#pragma unroll
    for (int s = 0; s < 2; s++) {
        cpa16(ast + s * bufA, Aptr + s * 16, asz);
        cpa16(bst0 + s * bufB, Bptr0 + s * 16, 16);
        cpa16(bst1 + s * bufB, Bptr1 + s * 16, 16);
        asm volatile("cp.async.commit_group;");
    }

    for (int it = 0; it < NT; it++) {
        const int buf = it % 3;
        asm volatile("cp.async.wait_group 1;");
        __syncthreads();

        if (it + 2 < NT) {
            const int off = (it + 2) * 16;
            const int nb = (it + 2) % 3;
            cpa16(ast + nb * bufA, Aptr + off, asz);
            cpa16(bst0 + nb * bufB, Bptr0 + off, 16);
            cpa16(bst1 + nb * bufB, Bptr1 + off, 16);
        }
        asm volatile("cp.async.commit_group;");

        uint32_t Af[2][4];
#pragma unroll
        for (int mt = 0; mt < 2; mt++)
            ldm_x4(Af[mt], sA_base + buf * bufA + aoff0 + mt * 16 * 48);

        uint32_t Bf[16][2];
#pragma unroll
        for (int q = 0; q < 8; q++) {
            uint32_t r[4];
            ldm_x4(r, sB_base + buf * bufB + boff0 + q * 16 * 48);
            Bf[2 * q][0]     = r[0]; Bf[2 * q][1]     = r[1];
            Bf[2 * q + 1][0] = r[2]; Bf[2 * q + 1][1] = r[3];
        }

#pragma unroll
        for (int nt = 0; nt < 16; nt++)
#pragma unroll
            for (int mt = 0; mt < 2; mt++)
                mma_f16(acc[mt][nt], Af[mt], Bf[nt][0], Bf[nt][1]);
    }

#pragma unroll
    for (int mt = 0; mt < 2; mt++) {
#pragma unroll
        for (int nt = 0; nt < 16; nt++) {
            int r = row0 + wm * 32 + mt * 16 + g;
            int c = wn * 128 + nt * 8 + 2 * tg;
            float c0 = acc[mt][nt][0], c1 = acc[mt][nt][1];
            float c2 = acc[mt][nt][2], c3 = acc[mt][nt][3];
            if (BIAS) {
                float b0 = bias[c], b1 = bias[c + 1];
                c0 += b0; c1 += b1; c2 += b0; c3 += b1;
            }
            if (r < M)     *(__half2*)(Cout + (size_t)r * HDIM + c)       = __floats2half2_rn(c0, c1);
            if (r + 8 < M) *(__half2*)(Cout + (size_t)(r + 8) * HDIM + c) = __floats2half2_rn(c2, c3);
        }
    }
}

// ---------------- gather core (8x unrolled) ----------------
__device__ __forceinline__ void gather_accum(float* acc, uint4 u, float w) {
    float2 p0 = __half22float2(*(const __half2*)&u.x);
    float2 p1 = __half22float2(*(const __half2*)&u.y);
    float2 p2 = __half22float2(*(const __half2*)&u.z);
    float2 p3 = __half22float2(*(const __half2*)&u.w);
    acc[0] = fmaf(w, p0.x, acc[0]); acc[1] = fmaf(w, p0.y, acc[1]);
    acc[2] = fmaf(w, p1.x, acc[2]); acc[3] = fmaf(w, p1.y, acc[3]);
    acc[4] = fmaf(w, p2.x, acc[4]); acc[5] = fmaf(w, p2.y, acc[5]);
    acc[6] = fmaf(w, p3.x, acc[6]); acc[7] = fmaf(w, p3.y, acc[7]);
}

__device__ __forceinline__ void gather_core(
    float* acc, const __half* __restrict__ hw, const int* __restrict__ offs,
    const int2* __restrict__ csr, int node, int col)
{
    const int beg = offs[node];
    const int end = offs[node + 1];

    int j = beg;
    for (; j + 7 < end; j += 8) {
        int2 e[8];
        uint4 u[8];
#pragma unroll
        for (int q = 0; q < 8; q++) e[q] = csr[j + q];
#pragma unroll
        for (int q = 0; q < 8; q++) u[q] = *(const uint4*)(hw + (size_t)e[q].x * HDIM + col);
#pragma unroll
        for (int q = 0; q < 8; q++) gather_accum(acc, u[q], __int_as_float(e[q].y));
    }
    for (; j + 1 < end; j += 2) {
        int2 e0 = csr[j], e1 = csr[j + 1];
        uint4 u0 = *(const uint4*)(hw + (size_t)e0.x * HDIM + col);
        uint4 u1 = *(const uint4*)(hw + (size_t)e1.x * HDIM + col);
        gather_accum(acc, u0, __int_as_float(e0.y));
        gather_accum(acc, u1, __int_as_float(e1.y));
    }
    if (j < end) {
        int2 e0 = csr[j];
        uint4 u0 = *(const uint4*)(hw + (size_t)e0.x * HDIM + col);
        gather_accum(acc, u0, __int_as_float(e0.y));
    }
}

__device__ __forceinline__ void gather_final(
    float* o, const float* acc, const __half* __restrict__ hw,
    const float* __restrict__ bias, const float* __restrict__ dinv, int node, int col)
{
    const float dd = dinv[node];
    const float ds = dd * dd;
    uint4 su = *(const uint4*)(hw + (size_t)node * HDIM + col);
    float2 s0 = __half22float2(*(const __half2*)&su.x);
    float2 s1 = __half22float2(*(const __half2*)&su.y);
    float2 s2 = __half22float2(*(const __half2*)&su.z);
    float2 s3 = __half22float2(*(const __half2*)&su.w);
    float sf[8] = {s0.x, s0.y, s1.x, s1.y, s2.x, s2.y, s3.x, s3.y};

    float4 bb0 = *(const float4*)(bias + col);
    float4 bb1 = *(const float4*)(bias + col + 4);
    float bf[8] = {bb0.x, bb0.y, bb0.z, bb0.w, bb1.x, bb1.y, bb1.z, bb1.w};

#pragma unroll
    for (int i = 0; i < 8; i++)
        o[i] = fmaxf(fmaf(acc[i], dd, fmaf(sf[i], ds, bf[i])), 0.f);   // ReLU fused
}

// conv gather: fp16 store
__global__ void __launch_bounds__(256) gather_kernel(
    __half* __restrict__ out, const __half* __restrict__ hw,
    const int* __restrict__ offs, const int2* __restrict__ csr,
    const float* __restrict__ dinv, const float* __restrict__ bias, int M)
{
    const int node = blockIdx.x * 8 + (threadIdx.x >> 5);
    if (node >= M) return;
    const int lane = threadIdx.x & 31;
    const int col  = lane * 8;

    float acc[8];
#pragma unroll
    for (int i = 0; i < 8; i++) acc[i] = 0.f;
    gather_core(acc, hw, offs, csr, node, col);

    float o[8];
    gather_final(o, acc, hw, bias, dinv, node, col);

    __half2 h2[4];
#pragma unroll
    for (int i = 0; i < 4; i++) h2[i] = __floats2half2_rn(o[2*i], o[2*i+1]);
    *(uint4*)(out + (size_t)node * HDIM + col) = *(uint4*)h2;
}

// final gather + decoder fused
__global__ void __launch_bounds__(256) gather_dec_kernel(
    float* __restrict__ out, const __half* __restrict__ hw,
    const int* __restrict__ offs, const int2* __restrict__ csr,
    const float* __restrict__ dinv, const float* __restrict__ bias,
    const float* __restrict__ dw, const float* __restrict__ db, int M)
{
    const int node = blockIdx.x * 8 + (threadIdx.x >> 5);
    if (node >= M) return;
    const int lane = threadIdx.x & 31;
    const int col  = lane * 8;

    float acc[8];
#pragma unroll
    for (int i = 0; i < 8; i++) acc[i] = 0.f;
    gather_core(acc, hw, offs, csr, node, col);

    float o[8];
    gather_final(o, acc, hw, bias, dinv, node, col);

    float4 w0 = *(const float4*)(dw + col);
    float4 w1 = *(const float4*)(dw + col + 4);
    float s = o[0]*w0.x + o[1]*w0.y + o[2]*w0.z + o[3]*w0.w
            + o[4]*w1.x + o[5]*w1.y + o[6]*w1.z + o[7]*w1.w;
#pragma unroll
    for (int off = 16; off > 0; off >>= 1) s += __shfl_xor_sync(0xffffffffu, s, off);
    if (lane == 0) out[node] = s + db[0];
}

// ---------------- launch ----------------
extern "C" void kernel_launch(void* const* d_in, const int* in_sizes, int n_in,
                              void* d_out, int out_size)
{
    const float* x     = (const float*)d_in[0];
    const int*   ei    = (const int*)d_in[1];
    const float* enc_W = (const float*)d_in[2];
    const float* enc_b = (const float*)d_in[3];
    const float* W1    = (const float*)d_in[4];
    const float* b1    = (const float*)d_in[5];
    const float* W2    = (const float*)d_in[6];
    const float* b2    = (const float*)d_in[7];
    const float* W3    = (const float*)d_in[8];
    const float* b3    = (const float*)d_in[9];
    const float* decW  = (const float*)d_in[10];
    const float* decb  = (const float*)d_in[11];
    float* out = (float*)d_out;

    const int M = in_sizes[0] / 128;   // 50000
    const int E = in_sizes[1] / 2;     // 800000
    const int* src = ei;
    const int* dst = ei + E;

    float *dinv;
    __half *actA, *actB, *hwh, *WhBase;
    int *deg, *offs, *cur, *bsum;
    int2 *csr;
    cudaGetSymbolAddress((void**)&actA,   g_actA);
    cudaGetSymbolAddress((void**)&actB,   g_actB);
    cudaGetSymbolAddress((void**)&hwh,    g_hwh);
    cudaGetSymbolAddress((void**)&WhBase, g_Wh);
    cudaGetSymbolAddress((void**)&deg,    g_deg);
    cudaGetSymbolAddress((void**)&dinv,   g_dinv);
    cudaGetSymbolAddress((void**)&offs,   g_offs);
    cudaGetSymbolAddress((void**)&cur,    g_cur);
    cudaGetSymbolAddress((void**)&bsum,   g_bsum);
    cudaGetSymbolAddress((void**)&csr,    g_csr);

    // one-time setup on the FIRST (uncaptured correctness) call
    static cudaStream_t s2 = nullptr;
    static cudaEvent_t evA = nullptr, evB = nullptr;
    if (!s2) {
        cudaStreamCreateWithFlags(&s2, cudaStreamNonBlocking);
        cudaEventCreateWithFlags(&evA, cudaEventDisableTiming);
        cudaEventCreateWithFlags(&evB, cudaEventDisableTiming);
        cudaFuncSetAttribute(gemm_f16_kernel<128, true>,
                             cudaFuncAttributeMaxDynamicSharedMemorySize, GEMM_SMEM);
        cudaFuncSetAttribute(gemm_f16_kernel<256, false>,
                             cudaFuncAttributeMaxDynamicSharedMemorySize, GEMM_SMEM);
    }

    const int nb = (M + 255) / 256;

    // ---- fused prep (deg zero + wsplit + x16) on main stream ----
    const int prep_items = 229376 + 50000 + M * 32;
    prep_kernel<<<(prep_items + 255) / 256, 256>>>(enc_W, W1, W2, W3, WhBase, deg, x, hwh, M);
    cudaEventRecord(evA, 0);

    // ---- CSR chain on side stream (only gather1 depends on it) ----
    cudaStreamWaitEvent(s2, evA, 0);
    deg_count_kernel<<<(E + 255) / 256, 256, 0, s2>>>(deg, dst, E);
    scan1_kernel<<<nb, 256, 0, s2>>>(deg, offs, bsum, M);
    scan2_kernel<<<1, 256, 0, s2>>>(bsum, offs, nb, M);
    scan3_kernel<<<nb, 256, 0, s2>>>(offs, cur, dinv, deg, bsum, M);
    csr_fill_kernel<<<(E + 255) / 256, 256, 0, s2>>>(cur, csr, src, dst, dinv, E);
    cudaEventRecord(evB, s2);

    const int gb = (M + 127) / 128;
    const int gat_blocks = (M + 7) / 8;

    // ---- main stream: encoder + conv1 GEMM overlap the CSR chain ----
    gemm_f16_kernel<128, true><<<gb, 256, GEMM_SMEM>>>(hwh, WhBase, enc_b, actA, M);
    gemm_f16_kernel<256, false><<<gb, 256, GEMM_SMEM>>>(actA, WhBase + 65536, nullptr, hwh, M);

    // join: gather1 needs CSR
    cudaStreamWaitEvent(0, evB, 0);
    gather_kernel<<<gat_blocks, 256>>>(actB, hwh, offs, csr, dinv, b1, M);

    // conv2
    gemm_f16_kernel<256, false><<<gb, 256, GEMM_SMEM>>>(actB, WhBase + 2 * 65536, nullptr, hwh, M);
    gather_kernel<<<gat_blocks, 256>>>(actA, hwh, offs, csr, dinv, b2, M);

    // conv3 + fused gather/decoder
    gemm_f16_kernel<256, false><<<gb, 256, GEMM_SMEM>>>(actA, WhBase + 3 * 65536, nullptr, hwh, M);
    gather_dec_kernel<<<gat_blocks, 256>>>(out, hwh, offs, csr, dinv, b3, decW, decb, M);
}

// round 15
// speedup vs baseline: 1.0175x; 1.0175x over previous
#include <cuda_runtime.h>
#include <cuda_fp16.h>
#include <cstdint>

#define NNODES 50000
#define EDGES  800000
#define HDIM   256

// ---------------- scratch (no allocations allowed) ----------------
__device__ __half g_actA[NNODES * HDIM];
__device__ __half g_actB[NNODES * HDIM];
__device__ __half g_hwh[NNODES * HDIM];    // GEMM out for convs; also holds x16 for encoder
__device__ __half g_Wh[4][65536];
__device__ int    g_deg[NNODES];
__device__ float  g_dinv[NNODES];
__device__ int    g_offs[NNODES + 1];
__device__ int    g_cur[NNODES];
__device__ int    g_bsum[256];
__device__ int2   g_csr[EDGES];            // .x = src node, .y = dinv[src] bits

// ---------------- fused prep: deg_zero + 4x weight transpose + x->fp16 ----------------
__global__ void prep_kernel(const float* __restrict__ enc_W, const float* __restrict__ W1,
                            const float* __restrict__ W2, const float* __restrict__ W3,
                            __half* __restrict__ WhBase,
                            int* __restrict__ deg,
                            const float* __restrict__ x, __half* __restrict__ xh,
                            int M)
{
    int i = blockIdx.x * 256 + threadIdx.x;
    if (i < 229376) {
        const float* W; __half* Wh; int K; int idx;
        if (i < 32768)       { W = enc_W; Wh = WhBase;              K = 128; idx = i; }
        else if (i < 98304)  { W = W1;    Wh = WhBase + 65536;      K = 256; idx = i - 32768; }
        else if (i < 163840) { W = W2;    Wh = WhBase + 2 * 65536;  K = 256; idx = i - 98304; }
        else                 { W = W3;    Wh = WhBase + 3 * 65536;  K = 256; idx = i - 163840; }
        int n = idx / K, k = idx - n * K;
        Wh[idx] = __float2half_rn(W[k * 256 + n]);
    } else if (i < 279376) {
        int node = i - 229376;
        if (node < M) deg[node] = 0;
    } else {
        int f4 = i - 279376;
        if (f4 < M * 32) {
            float4 v = *(const float4*)(x + 4 * (size_t)f4);
            __half2 a = __floats2half2_rn(v.x, v.y);
            __half2 b = __floats2half2_rn(v.z, v.w);
            *(uint2*)(xh + 4 * (size_t)f4) = make_uint2(*(uint32_t*)&a, *(uint32_t*)&b);
        }
    }
}

__global__ void deg_count_kernel(int* __restrict__ deg, const int* __restrict__ dst, int E) {
    int e = blockIdx.x * blockDim.x + threadIdx.x;
    if (e < E) atomicAdd(&deg[dst[e]], 1);
}

// ---------------- 3-pass scan (multi-block); dinv fused into pass 3 ----------------
__global__ void scan1_kernel(const int* __restrict__ deg, int* __restrict__ offs,
                             int* __restrict__ bsum, int n)
{
    __shared__ int sh[256];
    const int t = threadIdx.x;
    const int i = blockIdx.x * 256 + t;
    int v = (i < n) ? deg[i] : 0;
    sh[t] = v;
    __syncthreads();
#pragma unroll
    for (int off = 1; off < 256; off <<= 1) {
        int x = (t >= off) ? sh[t - off] : 0;
        __syncthreads();
        sh[t] += x;
        __syncthreads();
    }
    if (i < n) offs[i] = sh[t] - v;
    if (t == 255) bsum[blockIdx.x] = sh[255];
}

__global__ void scan2_kernel(int* __restrict__ bsum, int* __restrict__ offs, int nb, int n)
{
    __shared__ int sh[256];
    const int t = threadIdx.x;
    int v = (t < nb) ? bsum[t] : 0;
    sh[t] = v;
    __syncthreads();
#pragma unroll
    for (int off = 1; off < 256; off <<= 1) {
        int x = (t >= off) ? sh[t - off] : 0;
        __syncthreads();
        sh[t] += x;
        __syncthreads();
    }
    if (t < nb) bsum[t] = sh[t] - v;
    if (t == 255) offs[n] = sh[255];
}

__global__ void scan3_kernel(int* __restrict__ offs, int* __restrict__ cur,
                             float* __restrict__ dinv, const int* __restrict__ deg,
                             const int* __restrict__ bsum, int n)
{
    int i = blockIdx.x * blockDim.x + threadIdx.x;
    if (i < n) {
        int o = offs[i] + bsum[i >> 8];
        offs[i] = o;
        cur[i]  = o;
        dinv[i] = rsqrtf((float)(deg[i] + 1));   // +1 self-loop
    }
}

// ---------------- CSR fill (packed src+weight) ----------------
__global__ void csr_fill_kernel(int* __restrict__ cur, int2* __restrict__ csr,
                                const int* __restrict__ src, const int* __restrict__ dst,
                                const float* __restrict__ dinv, int E)
{
    int e = blockIdx.x * blockDim.x + threadIdx.x;
    if (e >= E) return;
    int s = src[e];
    int p = atomicAdd(&cur[dst[e]], 1);
    csr[p] = make_int2(s, __float_as_int(dinv[s]));
}

// ---------------- fp16 tensor-core GEMM: 128x128 tile, 3-stage cp.async + ldmatrix ----------------
// (proven R13 config: 2 CTAs/SM, static smem, dual-CTA latency hiding)
__device__ __forceinline__ void mma_f16(float* c, const uint32_t* a, uint32_t b0, uint32_t b1) {
    asm volatile("mma.sync.aligned.m16n8k16.row.col.f32.f16.f16.f32 "
        "{%0,%1,%2,%3}, {%4,%5,%6,%7}, {%8,%9}, {%0,%1,%2,%3};"
        : "+f"(c[0]), "+f"(c[1]), "+f"(c[2]), "+f"(c[3])
        : "r"(a[0]), "r"(a[1]), "r"(a[2]), "r"(a[3]), "r"(b0), "r"(b1));
}

__device__ __forceinline__ void ldm_x4(uint32_t* r, uint32_t saddr) {
    asm volatile("ldmatrix.sync.aligned.m8n8.x4.shared.b16 {%0,%1,%2,%3}, [%4];"
        : "=r"(r[0]), "=r"(r[1]), "=r"(r[2]), "=r"(r[3]) : "r"(saddr));
}

__device__ __forceinline__ void cpa16(uint32_t saddr, const void* gaddr, int szr) {
    asm volatile("cp.async.cg.shared.global [%0], [%1], 16, %2;"
        :: "r"(saddr), "l"(gaddr), "r"(szr));
}

template <int K, bool BIAS>
__global__ void __launch_bounds__(256) gemm_f16_kernel(
    const __half* __restrict__ A, const __half* __restrict__ Wh,
    const float* __restrict__ bias, __half* __restrict__ Cout, int M)
{
    __shared__ __half sA[3][128][24];
    __shared__ __half sB[3][128][24];

    const int tid  = threadIdx.x;
    const int lane = tid & 31;
    const int wid  = tid >> 5;
    const int wm   = wid >> 1;
    const int wn   = wid & 1;
    const int g    = lane >> 2;
    const int tg   = lane & 3;
    const int row0 = blockIdx.x * 128;
    const int col0 = blockIdx.y * 128;

    const int ar  = tid >> 1;
    const int ak8 = (tid & 1) * 8;
    const int bn  = tid & 127;
    const int bh8 = (tid >> 7) * 8;

    const int arow = row0 + ar;
    const int asz  = (arow < M) ? 16 : 0;
    const __half* Aptr = A + (size_t)arow * K + ak8;
    const __half* Bph  = Wh + (size_t)(col0 + bn) * K + bh8;

    const uint32_t sA_base = (uint32_t)__cvta_generic_to_shared(&sA[0][0][0]);
    const uint32_t sB_base = (uint32_t)__cvta_generic_to_shared(&sB[0][0][0]);
    const uint32_t bufstride = 128 * 48;
    const uint32_t ast = sA_base + ar * 48 + ak8 * 2;
    const uint32_t bst = sB_base + bn * 48 + bh8 * 2;

    const int l8 = lane & 7;
    const int a_r = ((lane >> 3) & 1) * 8 + l8;
    const int a_k = (lane >> 4) * 8;
    const int b_n = ((lane >> 4) & 1) * 8 + l8;
    const int b_k = ((lane >> 3) & 1) * 8;
    const uint32_t aoff0 = (uint32_t)((wm * 32 + a_r) * 48 + a_k * 2);
    const uint32_t boff0 = (uint32_t)((wn * 64 + b_n) * 48 + b_k * 2);

    float acc[2][8][4];
#pragma unroll
    for (int mt = 0; mt < 2; mt++)
#pragma unroll
        for (int nt = 0; nt < 8; nt++)
#pragma unroll
            for (int r = 0; r < 4; r++) acc[mt][nt][r] = 0.f;

    const int NT = K / 16;

#pragma unroll
    for (int s = 0; s < 2; s++) {
        const uint32_t nb = s * bufstride;
        cpa16(ast + nb, Aptr + s * 16, asz);
        cpa16(bst + nb, Bph + s * 16, 16);
        asm volatile("cp.async.commit_group;");
    }

    for (int it = 0; it < NT; it++) {
        const int buf = it % 3;
        asm volatile("cp.async.wait_group 1;");
        __syncthreads();

        if (it + 2 < NT) {
            const int off = (it + 2) * 16;
            const uint32_t nb = ((it + 2) % 3) * bufstride;
            cpa16(ast + nb, Aptr + off, asz);
            cpa16(bst + nb, Bph + off, 16);
        }
        asm volatile("cp.async.commit_group;");

        uint32_t Af[2][4];
#pragma unroll
        for (int mt = 0; mt < 2; mt++)
            ldm_x4(Af[mt], sA_base + buf * bufstride + aoff0 + mt * 16 * 48);

        uint32_t Bf[8][2];
#pragma unroll
        for (int q = 0; q < 4; q++) {
            uint32_t r[4];
            ldm_x4(r, sB_base + buf * bufstride + boff0 + q * 16 * 48);
            Bf[2 * q][0]     = r[0]; Bf[2 * q][1]     = r[1];
            Bf[2 * q + 1][0] = r[2]; Bf[2 * q + 1][1] = r[3];
        }

#pragma unroll
        for (int nt = 0; nt < 8; nt++)
#pragma unroll
            for (int mt = 0; mt < 2; mt++)
                mma_f16(acc[mt][nt], Af[mt], Bf[nt][0], Bf[nt][1]);
    }

#pragma unroll
    for (int mt = 0; mt < 2; mt++) {
#pragma unroll
        for (int nt = 0; nt < 8; nt++) {
            int r = row0 + wm * 32 + mt * 16 + g;
            int c = col0 + wn * 64 + nt * 8 + 2 * tg;
            float c0 = acc[mt][nt][0], c1 = acc[mt][nt][1];
            float c2 = acc[mt][nt][2], c3 = acc[mt][nt][3];
            if (BIAS) {
                float b0 = bias[c], b1 = bias[c + 1];
                c0 += b0; c1 += b1; c2 += b0; c3 += b1;
            }
            if (r < M)     *(__half2*)(Cout + (size_t)r * HDIM + c)       = __floats2half2_rn(c0, c1);
            if (r + 8 < M) *(__half2*)(Cout + (size_t)(r + 8) * HDIM + c) = __floats2half2_rn(c2, c3);
        }
    }
}

// ---------------- gather core (8x unrolled) ----------------
__device__ __forceinline__ void gather_accum(float* acc, uint4 u, float w) {
    float2 p0 = __half22float2(*(const __half2*)&u.x);
    float2 p1 = __half22float2(*(const __half2*)&u.y);
    float2 p2 = __half22float2(*(const __half2*)&u.z);
    float2 p3 = __half22float2(*(const __half2*)&u.w);
    acc[0] = fmaf(w, p0.x, acc[0]); acc[1] = fmaf(w, p0.y, acc[1]);
    acc[2] = fmaf(w, p1.x, acc[2]); acc[3] = fmaf(w, p1.y, acc[3]);
    acc[4] = fmaf(w, p2.x, acc[4]); acc[5] = fmaf(w, p2.y, acc[5]);
    acc[6] = fmaf(w, p3.x, acc[6]); acc[7] = fmaf(w, p3.y, acc[7]);
}

__device__ __forceinline__ void gather_core(
    float* acc, const __half* __restrict__ hw, const int* __restrict__ offs,
    const int2* __restrict__ csr, int node, int col)
{
    const int beg = offs[node];
    const int end = offs[node + 1];

    int j = beg;
    for (; j + 7 < end; j += 8) {
        int2 e[8];
        uint4 u[8];
#pragma unroll
        for (int q = 0; q < 8; q++) e[q] = csr[j + q];
#pragma unroll
        for (int q = 0; q < 8; q++) u[q] = *(const uint4*)(hw + (size_t)e[q].x * HDIM + col);
#pragma unroll
        for (int q = 0; q < 8; q++) gather_accum(acc, u[q], __int_as_float(e[q].y));
    }
    for (; j + 1 < end; j += 2) {
        int2 e0 = csr[j], e1 = csr[j + 1];
        uint4 u0 = *(const uint4*)(hw + (size_t)e0.x * HDIM + col);
        uint4 u1 = *(const uint4*)(hw + (size_t)e1.x * HDIM + col);
        gather_accum(acc, u0, __int_as_float(e0.y));
        gather_accum(acc, u1, __int_as_float(e1.y));
    }
    if (j < end) {
        int2 e0 = csr[j];
        uint4 u0 = *(const uint4*)(hw + (size_t)e0.x * HDIM + col);
        gather_accum(acc, u0, __int_as_float(e0.y));
    }
}

__device__ __forceinline__ void gather_final(
    float* o, const float* acc, const __half* __restrict__ hw,
    const float* __restrict__ bias, const float* __restrict__ dinv, int node, int col)
{
    const float dd = dinv[node];
    const float ds = dd * dd;
    uint4 su = *(const uint4*)(hw + (size_t)node * HDIM + col);
    float2 s0 = __half22float2(*(const __half2*)&su.x);
    float2 s1 = __half22float2(*(const __half2*)&su.y);
    float2 s2 = __half22float2(*(const __half2*)&su.z);
    float2 s3 = __half22float2(*(const __half2*)&su.w);
    float sf[8] = {s0.x, s0.y, s1.x, s1.y, s2.x, s2.y, s3.x, s3.y};

    float4 bb0 = *(const float4*)(bias + col);
    float4 bb1 = *(const float4*)(bias + col + 4);
    float bf[8] = {bb0.x, bb0.y, bb0.z, bb0.w, bb1.x, bb1.y, bb1.z, bb1.w};

#pragma unroll
    for (int i = 0; i < 8; i++)
        o[i] = fmaxf(fmaf(acc[i], dd, fmaf(sf[i], ds, bf[i])), 0.f);   // ReLU fused
}

// conv gather: fp16 store
__global__ void __launch_bounds__(256) gather_kernel(
    __half* __restrict__ out, const __half* __restrict__ hw,
    const int* __restrict__ offs, const int2* __restrict__ csr,
    const float* __restrict__ dinv, const float* __restrict__ bias, int M)
{
    const int node = blockIdx.x * 8 + (threadIdx.x >> 5);
    if (node >= M) return;
    const int lane = threadIdx.x & 31;
    const int col  = lane * 8;

    float acc[8];
#pragma unroll
    for (int i = 0; i < 8; i++) acc[i] = 0.f;
    gather_core(acc, hw, offs, csr, node, col);

    float o[8];
    gather_final(o, acc, hw, bias, dinv, node, col);

    __half2 h2[4];
#pragma unroll
    for (int i = 0; i < 4; i++) h2[i] = __floats2half2_rn(o[2*i], o[2*i+1]);
    *(uint4*)(out + (size_t)node * HDIM + col) = *(uint4*)h2;
}

// final gather + decoder fused
__global__ void __launch_bounds__(256) gather_dec_kernel(
    float* __restrict__ out, const __half* __restrict__ hw,
    const int* __restrict__ offs, const int2* __restrict__ csr,
    const float* __restrict__ dinv, const float* __restrict__ bias,
    const float* __restrict__ dw, const float* __restrict__ db, int M)
{
    const int node = blockIdx.x * 8 + (threadIdx.x >> 5);
    if (node >= M) return;
    const int lane = threadIdx.x & 31;
    const int col  = lane * 8;

    float acc[8];
#pragma unroll
    for (int i = 0; i < 8; i++) acc[i] = 0.f;
    gather_core(acc, hw, offs, csr, node, col);

    float o[8];
    gather_final(o, acc, hw, bias, dinv, node, col);

    float4 w0 = *(const float4*)(dw + col);
    float4 w1 = *(const float4*)(dw + col + 4);
    float s = o[0]*w0.x + o[1]*w0.y + o[2]*w0.z + o[3]*w0.w
            + o[4]*w1.x + o[5]*w1.y + o[6]*w1.z + o[7]*w1.w;
#pragma unroll
    for (int off = 16; off > 0; off >>= 1) s += __shfl_xor_sync(0xffffffffu, s, off);
    if (lane == 0) out[node] = s + db[0];
}

// ---------------- launch ----------------
extern "C" void kernel_launch(void* const* d_in, const int* in_sizes, int n_in,
                              void* d_out, int out_size)
{
    const float* x     = (const float*)d_in[0];
    const int*   ei    = (const int*)d_in[1];
    const float* enc_W = (const float*)d_in[2];
    const float* enc_b = (const float*)d_in[3];
    const float* W1    = (const float*)d_in[4];
    const float* b1    = (const float*)d_in[5];
    const float* W2    = (const float*)d_in[6];
    const float* b2    = (const float*)d_in[7];
    const float* W3    = (const float*)d_in[8];
    const float* b3    = (const float*)d_in[9];
    const float* decW  = (const float*)d_in[10];
    const float* decb  = (const float*)d_in[11];
    float* out = (float*)d_out;

    const int M = in_sizes[0] / 128;   // 50000
    const int E = in_sizes[1] / 2;     // 800000
    const int* src = ei;
    const int* dst = ei + E;

    float *dinv;
    __half *actA, *actB, *hwh, *WhBase;
    int *deg, *offs, *cur, *bsum;
    int2 *csr;
    cudaGetSymbolAddress((void**)&actA,   g_actA);
    cudaGetSymbolAddress((void**)&actB,   g_actB);
    cudaGetSymbolAddress((void**)&hwh,    g_hwh);
    cudaGetSymbolAddress((void**)&WhBase, g_Wh);
    cudaGetSymbolAddress((void**)&deg,    g_deg);
    cudaGetSymbolAddress((void**)&dinv,   g_dinv);
    cudaGetSymbolAddress((void**)&offs,   g_offs);
    cudaGetSymbolAddress((void**)&cur,    g_cur);
    cudaGetSymbolAddress((void**)&bsum,   g_bsum);
    cudaGetSymbolAddress((void**)&csr,    g_csr);

    // lazily created on the FIRST (uncaptured correctness) call; reused in capture
    static cudaStream_t s2 = nullptr;
    static cudaEvent_t evA = nullptr, evB = nullptr;
    if (!s2) {
        cudaStreamCreateWithFlags(&s2, cudaStreamNonBlocking);
        cudaEventCreateWithFlags(&evA, cudaEventDisableTiming);
        cudaEventCreateWithFlags(&evB, cudaEventDisableTiming);
    }

    const int nb = (M + 255) / 256;

    // ---- fused prep (deg zero + wsplit + x16) on main stream ----
    const int prep_items = 229376 + 50000 + M * 32;
    prep_kernel<<<(prep_items + 255) / 256, 256>>>(enc_W, W1, W2, W3, WhBase, deg, x, hwh, M);
    cudaEventRecord(evA, 0);

    // ---- CSR chain on side stream (only gather1 depends on it) ----
    cudaStreamWaitEvent(s2, evA, 0);
    deg_count_kernel<<<(E + 255) / 256, 256, 0, s2>>>(deg, dst, E);
    scan1_kernel<<<nb, 256, 0, s2>>>(deg, offs, bsum, M);
    scan2_kernel<<<1, 256, 0, s2>>>(bsum, offs, nb, M);
    scan3_kernel<<<nb, 256, 0, s2>>>(offs, cur, dinv, deg, bsum, M);
    csr_fill_kernel<<<(E + 255) / 256, 256, 0, s2>>>(cur, csr, src, dst, dinv, E);
    cudaEventRecord(evB, s2);

    const dim3 gg((M + 127) / 128, 2);
    const int gat_blocks = (M + 7) / 8;

    // ---- main stream: encoder + conv1 GEMM overlap the CSR chain ----
    gemm_f16_kernel<128, true><<<gg, 256>>>(hwh, WhBase, enc_b, actA, M);
    gemm_f16_kernel<256, false><<<gg, 256>>>(actA, WhBase + 65536, nullptr, hwh, M);

    // join: gather1 needs CSR
    cudaStreamWaitEvent(0, evB, 0);
    gather_kernel<<<gat_blocks, 256>>>(actB, hwh, offs, csr, dinv, b1, M);

    // conv2
    gemm_f16_kernel<256, false><<<gg, 256>>>(actB, WhBase + 2 * 65536, nullptr, hwh, M);
    gather_kernel<<<gat_blocks, 256>>>(actA, hwh, offs, csr, dinv, b2, M);

    // conv3 + fused gather/decoder
    gemm_f16_kernel<256, false><<<gg, 256>>>(actA, WhBase + 3 * 65536, nullptr, hwh, M);
    gather_dec_kernel<<<gat_blocks, 256>>>(out, hwh, offs, csr, dinv, b3, decW, decb, M);
}

// round 17
// speedup vs baseline: 1.0675x; 1.0492x over previous
#include <cuda_runtime.h>
#include <cuda_fp16.h>
#include <cstdint>

#define NNODES 50000
#define EDGES  800000
#define HDIM   256

// ---------------- scratch (no allocations allowed) ----------------
__device__ __half g_actA[NNODES * HDIM];
__device__ __half g_actB[NNODES * HDIM];
__device__ __half g_hwh[NNODES * HDIM];    // GEMM out for convs; also holds x16 for encoder
__device__ __half g_Wh[4][65536];
__device__ int    g_deg[NNODES];
__device__ float  g_dinv[NNODES];
__device__ int    g_offs[NNODES + 1];
__device__ int    g_cur[NNODES];
__device__ int    g_bsum[256];
__device__ int2   g_csr[EDGES];            // .x = src node, .y = dinv[src] bits

// ---------------- fused prep: deg_zero + 4x weight transpose + x->fp16 ----------------
__global__ void prep_kernel(const float* __restrict__ enc_W, const float* __restrict__ W1,
                            const float* __restrict__ W2, const float* __restrict__ W3,
                            __half* __restrict__ WhBase,
                            int* __restrict__ deg,
                            const float* __restrict__ x, __half* __restrict__ xh,
                            int M)
{
    int i = blockIdx.x * 256 + threadIdx.x;
    if (i < 229376) {
        const float* W; __half* Wh; int K; int idx;
        if (i < 32768)       { W = enc_W; Wh = WhBase;              K = 128; idx = i; }
        else if (i < 98304)  { W = W1;    Wh = WhBase + 65536;      K = 256; idx = i - 32768; }
        else if (i < 163840) { W = W2;    Wh = WhBase + 2 * 65536;  K = 256; idx = i - 98304; }
        else                 { W = W3;    Wh = WhBase + 3 * 65536;  K = 256; idx = i - 163840; }
        int n = idx / K, k = idx - n * K;
        Wh[idx] = __float2half_rn(W[k * 256 + n]);
    } else if (i < 279376) {
        int node = i - 229376;
        if (node < M) deg[node] = 0;
    } else {
        int f4 = i - 279376;
        if (f4 < M * 32) {
            float4 v = *(const float4*)(x + 4 * (size_t)f4);
            __half2 a = __floats2half2_rn(v.x, v.y);
            __half2 b = __floats2half2_rn(v.z, v.w);
            *(uint2*)(xh + 4 * (size_t)f4) = make_uint2(*(uint32_t*)&a, *(uint32_t*)&b);
        }
    }
}

__global__ void deg_count_kernel(int* __restrict__ deg, const int* __restrict__ dst, int E) {
    int e = blockIdx.x * blockDim.x + threadIdx.x;
    if (e < E) atomicAdd(&deg[dst[e]], 1);
}

// ---------------- 3-pass scan (multi-block); dinv fused into pass 3 ----------------
__global__ void scan1_kernel(const int* __restrict__ deg, int* __restrict__ offs,
                             int* __restrict__ bsum, int n)
{
    __shared__ int sh[256];
    const int t = threadIdx.x;
    const int i = blockIdx.x * 256 + t;
    int v = (i < n) ? deg[i] : 0;
    sh[t] = v;
    __syncthreads();
#pragma unroll
    for (int off = 1; off < 256; off <<= 1) {
        int x = (t >= off) ? sh[t - off] : 0;
        __syncthreads();
        sh[t] += x;
        __syncthreads();
    }
    if (i < n) offs[i] = sh[t] - v;
    if (t == 255) bsum[blockIdx.x] = sh[255];
}

__global__ void scan2_kernel(int* __restrict__ bsum, int* __restrict__ offs, int nb, int n)
{
    __shared__ int sh[256];
    const int t = threadIdx.x;
    int v = (t < nb) ? bsum[t] : 0;
    sh[t] = v;
    __syncthreads();
#pragma unroll
    for (int off = 1; off < 256; off <<= 1) {
        int x = (t >= off) ? sh[t - off] : 0;
        __syncthreads();
        sh[t] += x;
        __syncthreads();
    }
    if (t < nb) bsum[t] = sh[t] - v;
    if (t == 255) offs[n] = sh[255];
}

__global__ void scan3_kernel(int* __restrict__ offs, int* __restrict__ cur,
                             float* __restrict__ dinv, const int* __restrict__ deg,
                             const int* __restrict__ bsum, int n)
{
    int i = blockIdx.x * blockDim.x + threadIdx.x;
    if (i < n) {
        int o = offs[i] + bsum[i >> 8];
        offs[i] = o;
        cur[i]  = o;
        dinv[i] = rsqrtf((float)(deg[i] + 1));   // +1 self-loop
    }
}

// ---------------- CSR fill (packed src+weight) ----------------
__global__ void csr_fill_kernel(int* __restrict__ cur, int2* __restrict__ csr,
                                const int* __restrict__ src, const int* __restrict__ dst,
                                const float* __restrict__ dinv, int E)
{
    int e = blockIdx.x * blockDim.x + threadIdx.x;
    if (e >= E) return;
    int s = src[e];
    int p = atomicAdd(&cur[dst[e]], 1);
    csr[p] = make_int2(s, __float_as_int(dinv[s]));
}

// ---------------- fp16 tensor-core GEMM: 128x128 tile, 3-stage cp.async + ldmatrix ----------------
// (proven R13 config: 2 CTAs/SM, static smem, dual-CTA latency hiding)
// PDL: grid-dependency sync before first dependent global read.
__device__ __forceinline__ void mma_f16(float* c, const uint32_t* a, uint32_t b0, uint32_t b1) {
    asm volatile("mma.sync.aligned.m16n8k16.row.col.f32.f16.f16.f32 "
        "{%0,%1,%2,%3}, {%4,%5,%6,%7}, {%8,%9}, {%0,%1,%2,%3};"
        : "+f"(c[0]), "+f"(c[1]), "+f"(c[2]), "+f"(c[3])
        : "r"(a[0]), "r"(a[1]), "r"(a[2]), "r"(a[3]), "r"(b0), "r"(b1));
}

__device__ __forceinline__ void ldm_x4(uint32_t* r, uint32_t saddr) {
    asm volatile("ldmatrix.sync.aligned.m8n8.x4.shared.b16 {%0,%1,%2,%3}, [%4];"
        : "=r"(r[0]), "=r"(r[1]), "=r"(r[2]), "=r"(r[3]) : "r"(saddr));
}

__device__ __forceinline__ void cpa16(uint32_t saddr, const void* gaddr, int szr) {
    asm volatile("cp.async.cg.shared.global [%0], [%1], 16, %2;"
        :: "r"(saddr), "l"(gaddr), "r"(szr));
}

template <int K, bool BIAS>
__global__ void __launch_bounds__(256) gemm_f16_kernel(
    const __half* __restrict__ A, const __half* __restrict__ Wh,
    const float* __restrict__ bias, __half* __restrict__ Cout, int M)
{
    __shared__ __half sA[3][128][24];
    __shared__ __half sB[3][128][24];

    const int tid  = threadIdx.x;
    const int lane = tid & 31;
    const int wid  = tid >> 5;
    const int wm   = wid >> 1;
    const int wn   = wid & 1;
    const int g    = lane >> 2;
    const int tg   = lane & 3;
    const int row0 = blockIdx.x * 128;
    const int col0 = blockIdx.y * 128;

    const int ar  = tid >> 1;
    const int ak8 = (tid & 1) * 8;
    const int bn  = tid & 127;
    const int bh8 = (tid >> 7) * 8;

    const int arow = row0 + ar;
    const int asz  = (arow < M) ? 16 : 0;
    const __half* Aptr = A + (size_t)arow * K + ak8;
    const __half* Bph  = Wh + (size_t)(col0 + bn) * K + bh8;

    const uint32_t sA_base = (uint32_t)__cvta_generic_to_shared(&sA[0][0][0]);
    const uint32_t sB_base = (uint32_t)__cvta_generic_to_shared(&sB[0][0][0]);
    const uint32_t bufstride = 128 * 48;
    const uint32_t ast = sA_base + ar * 48 + ak8 * 2;
    const uint32_t bst = sB_base + bn * 48 + bh8 * 2;

    const int l8 = lane & 7;
    const int a_r = ((lane >> 3) & 1) * 8 + l8;
    const int a_k = (lane >> 4) * 8;
    const int b_n = ((lane >> 4) & 1) * 8 + l8;
    const int b_k = ((lane >> 3) & 1) * 8;
    const uint32_t aoff0 = (uint32_t)((wm * 32 + a_r) * 48 + a_k * 2);
    const uint32_t boff0 = (uint32_t)((wn * 64 + b_n) * 48 + b_k * 2);

    float acc[2][8][4];
#pragma unroll
    for (int mt = 0; mt < 2; mt++)
#pragma unroll
        for (int nt = 0; nt < 8; nt++)
#pragma unroll
            for (int r = 0; r < 4; r++) acc[mt][nt][r] = 0.f;

    const int NT = K / 16;

    // wait for programmatic predecessor's writes (A) before first load
    cudaGridDependencySynchronize();

#pragma unroll
    for (int s = 0; s < 2; s++) {
        const uint32_t nb = s * bufstride;
        cpa16(ast + nb, Aptr + s * 16, asz);
        cpa16(bst + nb, Bph + s * 16, 16);
        asm volatile("cp.async.commit_group;");
    }

    for (int it = 0; it < NT; it++) {
        const int buf = it % 3;
        asm volatile("cp.async.wait_group 1;");
        __syncthreads();

        if (it + 2 < NT) {
            const int off = (it + 2) * 16;
            const uint32_t nb = ((it + 2) % 3) * bufstride;
            cpa16(ast + nb, Aptr + off, asz);
            cpa16(bst + nb, Bph + off, 16);
        }
        asm volatile("cp.async.commit_group;");

        uint32_t Af[2][4];
#pragma unroll
        for (int mt = 0; mt < 2; mt++)
            ldm_x4(Af[mt], sA_base + buf * bufstride + aoff0 + mt * 16 * 48);

        uint32_t Bf[8][2];
#pragma unroll
        for (int q = 0; q < 4; q++) {
            uint32_t r[4];
            ldm_x4(r, sB_base + buf * bufstride + boff0 + q * 16 * 48);
            Bf[2 * q][0]     = r[0]; Bf[2 * q][1]     = r[1];
            Bf[2 * q + 1][0] = r[2]; Bf[2 * q + 1][1] = r[3];
        }

#pragma unroll
        for (int nt = 0; nt < 8; nt++)
#pragma unroll
            for (int mt = 0; mt < 2; mt++)
                mma_f16(acc[mt][nt], Af[mt], Bf[nt][0], Bf[nt][1]);
    }

#pragma unroll
    for (int mt = 0; mt < 2; mt++) {
#pragma unroll
        for (int nt = 0; nt < 8; nt++) {
            int r = row0 + wm * 32 + mt * 16 + g;
            int c = col0 + wn * 64 + nt * 8 + 2 * tg;
            float c0 = acc[mt][nt][0], c1 = acc[mt][nt][1];
            float c2 = acc[mt][nt][2], c3 = acc[mt][nt][3];
            if (BIAS) {
                float b0 = bias[c], b1 = bias[c + 1];
                c0 += b0; c1 += b1; c2 += b0; c3 += b1;
            }
            if (r < M)     *(__half2*)(Cout + (size_t)r * HDIM + c)       = __floats2half2_rn(c0, c1);
            if (r + 8 < M) *(__half2*)(Cout + (size_t)(r + 8) * HDIM + c) = __floats2half2_rn(c2, c3);
        }
    }
}

// ---------------- gather core (4x unrolled — proven R13 config) ----------------
__device__ __forceinline__ void gather_accum(float* acc, uint4 u, float w) {
    float2 p0 = __half22float2(*(const __half2*)&u.x);
    float2 p1 = __half22float2(*(const __half2*)&u.y);
    float2 p2 = __half22float2(*(const __half2*)&u.z);
    float2 p3 = __half22float2(*(const __half2*)&u.w);
    acc[0] = fmaf(w, p0.x, acc[0]); acc[1] = fmaf(w, p0.y, acc[1]);
    acc[2] = fmaf(w, p1.x, acc[2]); acc[3] = fmaf(w, p1.y, acc[3]);
    acc[4] = fmaf(w, p2.x, acc[4]); acc[5] = fmaf(w, p2.y, acc[5]);
    acc[6] = fmaf(w, p3.x, acc[6]); acc[7] = fmaf(w, p3.y, acc[7]);
}

__device__ __forceinline__ void gather_core(
    float* acc, const __half* __restrict__ hw, const int* __restrict__ offs,
    const int2* __restrict__ csr, int node, int col)
{
    const int beg = offs[node];
    const int end = offs[node + 1];

    int j = beg;
    for (; j + 3 < end; j += 4) {
        int2 e0 = csr[j],     e1 = csr[j + 1];
        int2 e2 = csr[j + 2], e3 = csr[j + 3];
        uint4 u0 = *(const uint4*)(hw + (size_t)e0.x * HDIM + col);
        uint4 u1 = *(const uint4*)(hw + (size_t)e1.x * HDIM + col);
        uint4 u2 = *(const uint4*)(hw + (size_t)e2.x * HDIM + col);
        uint4 u3 = *(const uint4*)(hw + (size_t)e3.x * HDIM + col);
        gather_accum(acc, u0, __int_as_float(e0.y));
        gather_accum(acc, u1, __int_as_float(e1.y));
        gather_accum(acc, u2, __int_as_float(e2.y));
        gather_accum(acc, u3, __int_as_float(e3.y));
    }
    for (; j < end; j++) {
        int2 e0 = csr[j];
        uint4 u0 = *(const uint4*)(hw + (size_t)e0.x * HDIM + col);
        gather_accum(acc, u0, __int_as_float(e0.y));
    }
}

__device__ __forceinline__ void gather_final(
    float* o, const float* acc, const __half* __restrict__ hw,
    const float* __restrict__ bias, const float* __restrict__ dinv, int node, int col)
{
    const float dd = dinv[node];
    const float ds = dd * dd;
    uint4 su = *(const uint4*)(hw + (size_t)node * HDIM + col);
    float2 s0 = __half22float2(*(const __half2*)&su.x);
    float2 s1 = __half22float2(*(const __half2*)&su.y);
    float2 s2 = __half22float2(*(const __half2*)&su.z);
    float2 s3 = __half22float2(*(const __half2*)&su.w);
    float sf[8] = {s0.x, s0.y, s1.x, s1.y, s2.x, s2.y, s3.x, s3.y};

    float4 bb0 = *(const float4*)(bias + col);
    float4 bb1 = *(const float4*)(bias + col + 4);
    float bf[8] = {bb0.x, bb0.y, bb0.z, bb0.w, bb1.x, bb1.y, bb1.z, bb1.w};

#pragma unroll
    for (int i = 0; i < 8; i++)
        o[i] = fmaxf(fmaf(acc[i], dd, fmaf(sf[i], ds, bf[i])), 0.f);   // ReLU fused
}

// conv gather: fp16 store
__global__ void __launch_bounds__(256) gather_kernel(
    __half* __restrict__ out, const __half* __restrict__ hw,
    const int* __restrict__ offs, const int2* __restrict__ csr,
    const float* __restrict__ dinv, const float* __restrict__ bias, int M)
{
    const int node = blockIdx.x * 8 + (threadIdx.x >> 5);
    const int lane = threadIdx.x & 31;
    const int col  = lane * 8;

    // wait for producer GEMM's hw writes (offs/csr are event-guarded, earlier)
    cudaGridDependencySynchronize();
    if (node >= M) return;

    float acc[8];
#pragma unroll
    for (int i = 0; i < 8; i++) acc[i] = 0.f;
    gather_core(acc, hw, offs, csr, node, col);

    float o[8];
    gather_final(o, acc, hw, bias, dinv, node, col);

    __half2 h2[4];
#pragma unroll
    for (int i = 0; i < 4; i++) h2[i] = __floats2half2_rn(o[2*i], o[2*i+1]);
    *(uint4*)(out + (size_t)node * HDIM + col) = *(uint4*)h2;
}

// final gather + decoder fused
__global__ void __launch_bounds__(256) gather_dec_kernel(
    float* __restrict__ out, const __half* __restrict__ hw,
    const int* __restrict__ offs, const int2* __restrict__ csr,
    const float* __restrict__ dinv, const float* __restrict__ bias,
    const float* __restrict__ dw, const float* __restrict__ db, int M)
{
    const int node = blockIdx.x * 8 + (threadIdx.x >> 5);
    const int lane = threadIdx.x & 31;
    const int col  = lane * 8;

    cudaGridDependencySynchronize();
    if (node >= M) return;

    float acc[8];
#pragma unroll
    for (int i = 0; i < 8; i++) acc[i] = 0.f;
    gather_core(acc, hw, offs, csr, node, col);

    float o[8];
    gather_final(o, acc, hw, bias, dinv, node, col);

    float4 w0 = *(const float4*)(dw + col);
    float4 w1 = *(const float4*)(dw + col + 4);
    float s = o[0]*w0.x + o[1]*w0.y + o[2]*w0.z + o[3]*w0.w
            + o[4]*w1.x + o[5]*w1.y + o[6]*w1.z + o[7]*w1.w;
#pragma unroll
    for (int off = 16; off > 0; off >>= 1) s += __shfl_xor_sync(0xffffffffu, s, off);
    if (lane == 0) out[node] = s + db[0];
}

// ---------------- PDL launch helper ----------------
template <typename Kern, typename... Args>
static inline void launch_pdl(Kern k, dim3 grid, dim3 block, cudaStream_t st, Args... args) {
    cudaLaunchConfig_t cfg = {};
    cfg.gridDim = grid;
    cfg.blockDim = block;
    cfg.dynamicSmemBytes = 0;
    cfg.stream = st;
    cudaLaunchAttribute attr[1];
    attr[0].id = cudaLaunchAttributeProgrammaticStreamSerialization;
    attr[0].val.programmaticStreamSerializationAllowed = 1;
    cfg.attrs = attr;
    cfg.numAttrs = 1;
    cudaLaunchKernelEx(&cfg, k, args...);
}

// ---------------- launch ----------------
extern "C" void kernel_launch(void* const* d_in, const int* in_sizes, int n_in,
                              void* d_out, int out_size)
{
    const float* x     = (const float*)d_in[0];
    const int*   ei    = (const int*)d_in[1];
    const float* enc_W = (const float*)d_in[2];
    const float* enc_b = (const float*)d_in[3];
    const float* W1    = (const float*)d_in[4];
    const float* b1    = (const float*)d_in[5];
    const float* W2    = (const float*)d_in[6];
    const float* b2    = (const float*)d_in[7];
    const float* W3    = (const float*)d_in[8];
    const float* b3    = (const float*)d_in[9];
    const float* decW  = (const float*)d_in[10];
    const float* decb  = (const float*)d_in[11];
    float* out = (float*)d_out;

    const int M = in_sizes[0] / 128;   // 50000
    const int E = in_sizes[1] / 2;     // 800000
    const int* src = ei;
    const int* dst = ei + E;

    float *dinv;
    __half *actA, *actB, *hwh, *WhBase;
    int *deg, *offs, *cur, *bsum;
    int2 *csr;
    cudaGetSymbolAddress((void**)&actA,   g_actA);
    cudaGetSymbolAddress((void**)&actB,   g_actB);
    cudaGetSymbolAddress((void**)&hwh,    g_hwh);
    cudaGetSymbolAddress((void**)&WhBase, g_Wh);
    cudaGetSymbolAddress((void**)&deg,    g_deg);
    cudaGetSymbolAddress((void**)&dinv,   g_dinv);
    cudaGetSymbolAddress((void**)&offs,   g_offs);
    cudaGetSymbolAddress((void**)&cur,    g_cur);
    cudaGetSymbolAddress((void**)&bsum,   g_bsum);
    cudaGetSymbolAddress((void**)&csr,    g_csr);

    // lazily created on the FIRST (uncaptured correctness) call; reused in capture
    static cudaStream_t s2 = nullptr;
    static cudaEvent_t evA = nullptr, evB = nullptr;
    if (!s2) {
        cudaStreamCreateWithFlags(&s2, cudaStreamNonBlocking);
        cudaEventCreateWithFlags(&evA, cudaEventDisableTiming);
        cudaEventCreateWithFlags(&evB, cudaEventDisableTiming);
    }

    const int nb = (M + 255) / 256;

    // ---- fused prep (deg zero + wsplit + x16) on main stream ----
    const int prep_items = 229376 + 50000 + M * 32;
    prep_kernel<<<(prep_items + 255) / 256, 256>>>(enc_W, W1, W2, W3, WhBase, deg, x, hwh, M);
    cudaEventRecord(evA, 0);

    // ---- CSR chain on side stream (only gather1 depends on it) ----
    cudaStreamWaitEvent(s2, evA, 0);
    deg_count_kernel<<<(E + 255) / 256, 256, 0, s2>>>(deg, dst, E);
    scan1_kernel<<<nb, 256, 0, s2>>>(deg, offs, bsum, M);
    scan2_kernel<<<1, 256, 0, s2>>>(bsum, offs, nb, M);
    scan3_kernel<<<nb, 256, 0, s2>>>(offs, cur, dinv, deg, bsum, M);
    csr_fill_kernel<<<(E + 255) / 256, 256, 0, s2>>>(cur, csr, src, dst, dinv, E);
    cudaEventRecord(evB, s2);

    const dim3 gg((M + 127) / 128, 2);
    const dim3 blk(256, 1, 1);
    const int gat_blocks = (M + 7) / 8;

    // ---- main stream (PDL chain): encoder + conv1 GEMM overlap the CSR chain ----
    launch_pdl(gemm_f16_kernel<128, true>, gg, blk, (cudaStream_t)0,
               (const __half*)hwh, (const __half*)WhBase, enc_b, actA, M);
    launch_pdl(gemm_f16_kernel<256, false>, gg, blk, (cudaStream_t)0,
               (const __half*)actA, (const __half*)(WhBase + 65536), (const float*)nullptr, hwh, M);

    // join: gather1 needs CSR (hard event edge preserved under PDL)
    cudaStreamWaitEvent(0, evB, 0);
    launch_pdl(gather_kernel, dim3(gat_blocks), blk, (cudaStream_t)0,
               actB, (const __half*)hwh, (const int*)offs, (const int2*)csr,
               (const float*)dinv, b1, M);

    // conv2
    launch_pdl(gemm_f16_kernel<256, false>, gg, blk, (cudaStream_t)0,
               (const __half*)actB, (const __half*)(WhBase + 2 * 65536), (const float*)nullptr, hwh, M);
    launch_pdl(gather_kernel, dim3(gat_blocks), blk, (cudaStream_t)0,
               actA, (const __half*)hwh, (const int*)offs, (const int2*)csr,
               (const float*)dinv, b2, M);

    // conv3 + fused gather/decoder
    launch_pdl(gemm_f16_kernel<256, false>, gg, blk, (cudaStream_t)0,
               (const __half*)actA, (const __half*)(WhBase + 3 * 65536), (const float*)nullptr, hwh, M);
    launch_pdl(gather_dec_kernel, dim3(gat_blocks), blk, (cudaStream_t)0,
               out, (const __half*)hwh, (const int*)offs, (const int2*)csr,
               (const float*)dinv, b3, decW, decb, M);
}